// round 15
// baseline (speedup 1.0000x reference)
#include <cuda_runtime.h>
#include <cuda_bf16.h>
#include <cstdint>

// Problem constants
#define BB 128
#define SS 512
#define UU 1024
#define TT 48

#define KCH 16            // floats per k-chunk (one k16 mma step)
#define NCH (UU / KCH)    // 64 chunks
#define STG 4             // cp.async pipeline stages
#define RSTRIDE 20        // smem row stride in floats (pad: 2-way max conflicts)

// Scratch (device globals — no runtime allocation)
__device__ float g_scores[BB * SS * TT];            // fp32 scores, 12.6 MB
// W pre-baked into mma.sync B-fragment layout:
// [s2 (32)][j (6)][lane (32)] uint4 = {b0,b1 of k-step 2*s2, b0,b1 of 2*s2+1}
__device__ __align__(16) uint4 g_Wfrag[32 * 6 * 32];

__device__ __forceinline__ uint32_t smem_u32(const void* p) {
    uint32_t a;
    asm("{ .reg .u64 t; cvta.to.shared.u64 t, %1; cvt.u32.u64 %0, t; }"
        : "=r"(a) : "l"(p));
    return a;
}
__device__ __forceinline__ uint32_t packbf(float2 f) {
    __nv_bfloat162 h = __float22bfloat162_rn(f);
    return *reinterpret_cast<uint32_t*>(&h);
}
__device__ __forceinline__ void mma16816(float d[4],
                                         uint32_t a0, uint32_t a1,
                                         uint32_t a2, uint32_t a3,
                                         uint32_t b0, uint32_t b1) {
    asm volatile(
        "mma.sync.aligned.m16n8k16.row.col.f32.bf16.bf16.f32 "
        "{%0,%1,%2,%3}, {%4,%5,%6,%7}, {%8,%9}, {%0,%1,%2,%3};"
        : "+f"(d[0]), "+f"(d[1]), "+f"(d[2]), "+f"(d[3])
        : "r"(a0), "r"(a1), "r"(a2), "r"(a3), "r"(b0), "r"(b1));
}
__device__ __forceinline__ void cp16(uint32_t dst, const void* src) {
    asm volatile("cp.async.cg.shared.global [%0], [%1], 16;"
                 :: "r"(dst), "l"(src) : "memory");
}
#define CP_COMMIT() asm volatile("cp.async.commit_group;" ::: "memory")
#define CP_WAIT(n)  asm volatile("cp.async.wait_group %0;" :: "n"(n) : "memory")

// Packed fp32x2 FMA (Blackwell): d.lo += a.lo*b.lo, d.hi += a.hi*b.hi (exact fp32)
__device__ __forceinline__ void fma2(unsigned long long& d,
                                     unsigned long long a,
                                     unsigned long long b) {
    asm("fma.rn.f32x2 %0, %1, %2, %0;" : "+l"(d) : "l"(a), "l"(b));
}
__device__ __forceinline__ unsigned long long packf2(float a, float b) {
    float2 f = make_float2(a, b);
    return *reinterpret_cast<unsigned long long*>(&f);
}

// 48-elem dot: E pre-packed as 24 f32x2 pairs, vec from smem as ulonglong2.
// 24 FFMA2 (vs 48 FFMA) -> half the warp issue cost of the old dot48.
__device__ __forceinline__ float dot48p(const unsigned long long* Ep,
                                        const float* vec, float& first) {
    const ulonglong2* up = reinterpret_cast<const ulonglong2*>(vec);
    unsigned long long acc0 = 0ull, acc1 = 0ull, acc2 = 0ull, acc3 = 0ull;
    ulonglong2 u0 = up[0];
    first = __uint_as_float((uint32_t)(u0.x & 0xffffffffu));
    fma2(acc0, u0.x, Ep[0]);
    fma2(acc1, u0.y, Ep[1]);
#pragma unroll
    for (int j = 1; j < 12; j++) {
        ulonglong2 u = up[j];
        if (j & 1) { fma2(acc2, u.x, Ep[2 * j]); fma2(acc3, u.y, Ep[2 * j + 1]); }
        else       { fma2(acc0, u.x, Ep[2 * j]); fma2(acc1, u.y, Ep[2 * j + 1]); }
    }
    float2 f0 = *reinterpret_cast<float2*>(&acc0);
    float2 f1 = *reinterpret_cast<float2*>(&acc1);
    float2 f2 = *reinterpret_cast<float2*>(&acc2);
    float2 f3 = *reinterpret_cast<float2*>(&acc3);
    return ((f0.x + f0.y) + (f1.x + f1.y)) + ((f2.x + f2.y) + (f3.x + f3.y));
}

// ---------------------------------------------------------------------------
// One-shot: bake W [U][T] into B fragments (bf16) for mma.sync.
// ---------------------------------------------------------------------------
__global__ void wfrag_kernel(const float* __restrict__ W) {
    int idx = blockIdx.x * 256 + threadIdx.x;     // 0 .. 64*6*32-1
    if (idx >= 64 * 6 * 32) return;
    int lane = idx & 31;
    int j    = (idx >> 5) % 6;
    int s    = idx / (6 * 32);                    // k-step 0..63
    int c    = lane & 3;
    int n    = 8 * j + (lane >> 2);
    int k0   = 16 * s + 2 * c;
    uint32_t b0 = packbf(make_float2(W[(size_t)k0 * TT + n],
                                     W[(size_t)(k0 + 1) * TT + n]));
    uint32_t b1 = packbf(make_float2(W[(size_t)(k0 + 8) * TT + n],
                                     W[(size_t)(k0 + 9) * TT + n]));
    int s2 = s >> 1, h = s & 1;
    uint32_t* out = reinterpret_cast<uint32_t*>(&g_Wfrag[(s2 * 6 + j) * 32 + lane]);
    out[h * 2 + 0] = b0;
    out[h * 2 + 1] = b1;
}

// ---------------------------------------------------------------------------
// GEMM via mma.sync bf16 + cp.async 4-stage smem pipeline (R12-exact, 75us).
// ---------------------------------------------------------------------------
__global__ __launch_bounds__(256)
void gemm_mma(const float* __restrict__ H, const float* __restrict__ bias) {
    __shared__ __align__(16) float sA[STG * 128 * RSTRIDE];   // 40 KB

    const int tid  = threadIdx.x;
    const int w    = tid >> 5;
    const int lane = tid & 31;
    const int c    = lane & 3;
    const int g    = lane >> 2;

    const int crow  = tid >> 1;
    const int chalf = tid & 1;
    const float* gsrc = H + ((size_t)blockIdx.x * 128 + crow) * UU + chalf * 8;
    const uint32_t sbase = smem_u32(sA);
    const uint32_t cdst  = sbase + (crow * RSTRIDE + chalf * 8) * 4;

    const size_t m0 = (size_t)blockIdx.x * 128 + w * 16;
    const float* srow = sA + (w * 16 + g) * RSTRIDE + 2 * c;

    float2 bias2[6];
#pragma unroll
    for (int j = 0; j < 6; j++)
        bias2[j] = *reinterpret_cast<const float2*>(bias + 8 * j + 2 * c);

    float d[6][4];
#pragma unroll
    for (int j = 0; j < 6; j++)
#pragma unroll
        for (int i = 0; i < 4; i++) d[j][i] = 0.f;

#pragma unroll
    for (int ch = 0; ch < 3; ch++) {
        uint32_t dst = cdst + ch * (128 * RSTRIDE * 4);
        const float* src = gsrc + ch * KCH;
        cp16(dst, src);
        cp16(dst + 16, src + 4);
        CP_COMMIT();
    }

    for (int s2 = 0; s2 < 32; s2++) {
        uint4 bf[6];
        {
            const uint4* bp = g_Wfrag + (size_t)(s2 * 6) * 32 + lane;
#pragma unroll
            for (int j = 0; j < 6; j++) bf[j] = bp[j * 32];
        }
        {
            const int ch = 2 * s2;
            if (ch < NCH - 2) { CP_WAIT(2); } else { CP_WAIT(0); }
            __syncthreads();
            if (ch + 3 < NCH) {
                uint32_t dst = cdst + ((ch + 3) & 3) * (128 * RSTRIDE * 4);
                const float* src = gsrc + (ch + 3) * KCH;
                cp16(dst, src);
                cp16(dst + 16, src + 4);
                CP_COMMIT();
            }
            const float* sp = srow + (ch & 3) * (128 * RSTRIDE);
            float2 f0 = *reinterpret_cast<const float2*>(sp);
            float2 f1 = *reinterpret_cast<const float2*>(sp + 8 * RSTRIDE);
            float2 f2 = *reinterpret_cast<const float2*>(sp + 8);
            float2 f3 = *reinterpret_cast<const float2*>(sp + 8 * RSTRIDE + 8);
            uint32_t a0 = packbf(f0), a1 = packbf(f1);
            uint32_t a2 = packbf(f2), a3 = packbf(f3);
#pragma unroll
            for (int j = 0; j < 6; j++)
                mma16816(d[j], a0, a1, a2, a3, bf[j].x, bf[j].y);
        }
        {
            const int ch = 2 * s2 + 1;
            if (ch < NCH - 2) { CP_WAIT(2); } else { CP_WAIT(0); }
            __syncthreads();
            if (ch + 3 < NCH) {
                uint32_t dst = cdst + ((ch + 3) & 3) * (128 * RSTRIDE * 4);
                const float* src = gsrc + (ch + 3) * KCH;
                cp16(dst, src);
                cp16(dst + 16, src + 4);
                CP_COMMIT();
            }
            const float* sp = srow + (ch & 3) * (128 * RSTRIDE);
            float2 f0 = *reinterpret_cast<const float2*>(sp);
            float2 f1 = *reinterpret_cast<const float2*>(sp + 8 * RSTRIDE);
            float2 f2 = *reinterpret_cast<const float2*>(sp + 8);
            float2 f3 = *reinterpret_cast<const float2*>(sp + 8 * RSTRIDE + 8);
            uint32_t a0 = packbf(f0), a1 = packbf(f1);
            uint32_t a2 = packbf(f2), a3 = packbf(f3);
#pragma unroll
            for (int j = 0; j < 6; j++)
                mma16816(d[j], a0, a1, a2, a3, bf[j].z, bf[j].w);
        }
    }

    float* dst0 = g_scores + (m0 + g) * TT;
    float* dst1 = dst0 + 8 * TT;
#pragma unroll
    for (int j = 0; j < 6; j++) {
        *reinterpret_cast<float2*>(dst0 + 8 * j + 2 * c) =
            make_float2(d[j][0] + bias2[j].x, d[j][1] + bias2[j].y);
        *reinterpret_cast<float2*>(dst1 + 8 * j + 2 * c) =
            make_float2(d[j][2] + bias2[j].x, d[j][3] + bias2[j].y);
    }
}

// ---------------------------------------------------------------------------
// BIDIRECTIONAL fused scan + numerator (R14 structure; dot in packed f32x2).
// 160 threads/block:
//   threads 0-63  : forward  alpha scan, m = (len-1)/2 steps (E columns).
//   threads 64-127: backward beta  scan, K = len-1-m steps  (E rows).
//   threads 128-159: numerator, then spins exactly K+2 barriers.
// logZ = (Cf+Cb)·ln2 + log(sum_t alpha_m[t]·beta_m[t]);  out = num - logZ.
// ---------------------------------------------------------------------------
__global__ void scan_kernel(const float* __restrict__ trans,
                            const float* __restrict__ startT,
                            const float* __restrict__ endT,
                            const int* __restrict__ tag,
                            const int* __restrict__ s_len,
                            float* __restrict__ out) {
    const int b = blockIdx.x;
    const int t = threadIdx.x;
    __shared__ __align__(16) float fbuf[2][64];   // forward alpha (linear)
    __shared__ __align__(16) float bbuf[2][64];   // backward w / b (linear)
    __shared__ float redf[TT];
    __shared__ float redb[TT];
    __shared__ float s_num;
    __shared__ int   s_CeB;

    const int len = s_len[b];
    const int m   = (len - 1) >> 1;      // meeting point
    const int K   = len - 1 - m;         // loop length (K >= m, K-m in {0,1})
    const float* sc = g_scores + (size_t)b * SS * TT;

    if (t < 64) {
        // ---------------- FORWARD group: state t ----------------
        const bool act = t < TT;
        const int tc = act ? t : 0;

        unsigned long long Ep[24];
#pragma unroll
        for (int k = 0; k < 24; k++) {
            float e0 = __expf(trans[(2 * k) * TT + tc]);       // column t
            float e1 = __expf(trans[(2 * k + 1) * TT + tc]);
            Ep[k] = act ? packf2(e0, e1) : 0ull;
        }
        fbuf[0][t] = act ? __expf(startT[tc] + sc[tc]) : 0.f;
        int Ce = 0;

        float x1 = __expf(sc[1 * TT + tc]);
        float eA = sc[2 * TT + tc];
        float eB = sc[3 * TT + tc];
        __syncthreads();                               // barrier 1 (init)

        int cur = 0;
        for (int i = 0; i < K; ++i) {
            if (i < m) {
                const int s = i + 1;
                float ex = x1;
                x1 = __expf(eA); eA = eB;
                int sp = s + 3; if (sp > SS - 1) sp = SS - 1;
                eB = sc[sp * TT + tc];

                float v0;
                float dot = dot48p(Ep, fbuf[cur], v0);

                int eb = (__float_as_int(v0) >> 23) & 0xff;
                Ce += eb - 127;
                float sx = __int_as_float((254 - eb) << 23) * ex;

                fbuf[cur ^ 1][t] = dot * sx;
                cur ^= 1;
            }
            __syncthreads();                           // barriers 2..K+1
        }
        if (act) redf[t] = fbuf[cur][t];               // alpha_m (renormed)
        __syncthreads();                               // barrier K+2

        if (t == 0) {
            float ssum = 0.f;
#pragma unroll
            for (int k = 0; k < TT; k++) ssum += redf[k] * redb[k];
            float logZ = (float)(Ce + s_CeB) * 0.6931471805599453f + __logf(ssum);
            out[b] = s_num - logZ;
        }
    } else if (t < 128) {
        // ---------------- BACKWARD group: state u ----------------
        const int u = t - 64;
        const bool act = u < TT;
        const int uc = act ? u : 0;

        unsigned long long Ep[24];
#pragma unroll
        for (int k = 0; k < 24; k++) {
            float e0 = __expf(trans[uc * TT + 2 * k]);         // row u
            float e1 = __expf(trans[uc * TT + 2 * k + 1]);
            Ep[k] = act ? packf2(e0, e1) : 0ull;
        }
        // init w_{len-1} = exp(emit_{len-1} + end)
        bbuf[0][u] = act ? __expf(sc[(size_t)(len - 1) * TT + uc] + endT[uc]) : 0.f;
        int Ce = 0;

        int p1 = len - 2; if (p1 < 0) p1 = 0;
        int p2 = len - 3; if (p2 < 0) p2 = 0;
        int p3 = len - 4; if (p3 < 0) p3 = 0;
        float x1 = __expf(sc[(size_t)p1 * TT + uc]);
        float eA = sc[(size_t)p2 * TT + uc];
        float eB = sc[(size_t)p3 * TT + uc];
        __syncthreads();                               // barrier 1 (init)

        int cur = 0;
        for (int i = 0; i < K; ++i) {
            const int s = len - 2 - i;                 // s: len-2 .. m
            float ex = x1;
            x1 = __expf(eA); eA = eB;
            int sp = s - 3; if (sp < 0) sp = 0;
            eB = sc[(size_t)sp * TT + uc];

            float w0;
            float dot = dot48p(Ep, bbuf[cur], w0);     // b_s[u] = E_row_u · w_{s+1}

            int eb = (__float_as_int(w0) >> 23) & 0xff;
            Ce += eb - 127;
            float scale = __int_as_float((254 - eb) << 23);

            float val = (s > m) ? (dot * scale * ex)   // w_s = x_s ∘ b_s
                                : (dot * scale);       // final b_m (no x)
            bbuf[cur ^ 1][u] = val;
            cur ^= 1;
            __syncthreads();                           // barriers 2..K+1
        }
        if (act) redb[u] = K ? bbuf[cur][u]            // b_m (renormed)
                             : __expf(endT[uc]);       // len==1: beta = exp(end)
        if (u == 0) s_CeB = Ce;
        __syncthreads();                               // barrier K+2
    } else {
        // ---------------- numerator warp ----------------
        const int l = t - 128;
        const int* tg = tag + b * SS;
        float local = 0.f;
        for (int s = l; s < len; s += 32) {
            int tc2 = tg[s];
            local += sc[s * TT + tc2];
            if (s >= 1) local += trans[tg[s - 1] * TT + tc2];
        }
        if (l == 0) local += startT[tg[0]] + endT[tg[len - 1]];
#pragma unroll
        for (int o = 16; o > 0; o >>= 1)
            local += __shfl_down_sync(0xffffffffu, local, o);
        if (l == 0) s_num = local;

        for (int i = 0; i < K + 2; i++) __syncthreads();
    }
}

// ---------------------------------------------------------------------------
// Launch. Inputs: H, W, b, start_transitions, end_transitions, transitions,
// tag(int32), s_len(int32), w_mask (unused: mask == s < s_len).
// ---------------------------------------------------------------------------
extern "C" void kernel_launch(void* const* d_in, const int* in_sizes, int n_in,
                              void* d_out, int out_size) {
    const float* H      = (const float*)d_in[0];
    const float* W      = (const float*)d_in[1];
    const float* bias   = (const float*)d_in[2];
    const float* startT = (const float*)d_in[3];
    const float* endT   = (const float*)d_in[4];
    const float* trans  = (const float*)d_in[5];
    const int*   tag    = (const int*)d_in[6];
    const int*   s_len  = (const int*)d_in[7];
    (void)in_sizes; (void)n_in; (void)out_size;
    float* out = (float*)d_out;

    wfrag_kernel<<<48, 256>>>(W);
    gemm_mma<<<(BB * SS) / 128, 256>>>(H, bias);
    scan_kernel<<<BB, 160>>>(trans, startT, endT, tag, s_len, out);
}

// round 16
// speedup vs baseline: 1.3780x; 1.3780x over previous
#include <cuda_runtime.h>
#include <cuda_bf16.h>
#include <cstdint>

// Problem constants
#define BB 128
#define SS 512
#define UU 1024
#define TT 48

#define KCH 16            // floats per k-chunk (one k16 mma step)
#define NCH (UU / KCH)    // 64 chunks
#define STG 4             // cp.async pipeline stages
#define RSTRIDE 20        // smem row stride in floats (pad: 2-way max conflicts)

// Scratch (device globals — no runtime allocation)
__device__ float g_scores[BB * SS * TT];            // fp32 scores, 12.6 MB
// W pre-baked into mma.sync B-fragment layout:
// [s2 (32)][j (6)][lane (32)] uint4 = {b0,b1 of k-step 2*s2, b0,b1 of 2*s2+1}
__device__ __align__(16) uint4 g_Wfrag[32 * 6 * 32];

__device__ __forceinline__ uint32_t smem_u32(const void* p) {
    uint32_t a;
    asm("{ .reg .u64 t; cvta.to.shared.u64 t, %1; cvt.u32.u64 %0, t; }"
        : "=r"(a) : "l"(p));
    return a;
}
__device__ __forceinline__ uint32_t packbf(float2 f) {
    __nv_bfloat162 h = __float22bfloat162_rn(f);
    return *reinterpret_cast<uint32_t*>(&h);
}
__device__ __forceinline__ void mma16816(float d[4],
                                         uint32_t a0, uint32_t a1,
                                         uint32_t a2, uint32_t a3,
                                         uint32_t b0, uint32_t b1) {
    asm volatile(
        "mma.sync.aligned.m16n8k16.row.col.f32.bf16.bf16.f32 "
        "{%0,%1,%2,%3}, {%4,%5,%6,%7}, {%8,%9}, {%0,%1,%2,%3};"
        : "+f"(d[0]), "+f"(d[1]), "+f"(d[2]), "+f"(d[3])
        : "r"(a0), "r"(a1), "r"(a2), "r"(a3), "r"(b0), "r"(b1));
}
__device__ __forceinline__ void cp16(uint32_t dst, const void* src) {
    asm volatile("cp.async.cg.shared.global [%0], [%1], 16;"
                 :: "r"(dst), "l"(src) : "memory");
}
#define CP_COMMIT() asm volatile("cp.async.commit_group;" ::: "memory")
#define CP_WAIT(n)  asm volatile("cp.async.wait_group %0;" :: "n"(n) : "memory")

// ---------------------------------------------------------------------------
// One-shot: bake W [U][T] into B fragments (bf16) for mma.sync.
// ---------------------------------------------------------------------------
__global__ void wfrag_kernel(const float* __restrict__ W) {
    int idx = blockIdx.x * 256 + threadIdx.x;     // 0 .. 64*6*32-1
    if (idx >= 64 * 6 * 32) return;
    int lane = idx & 31;
    int j    = (idx >> 5) % 6;
    int s    = idx / (6 * 32);                    // k-step 0..63
    int c    = lane & 3;
    int n    = 8 * j + (lane >> 2);
    int k0   = 16 * s + 2 * c;
    uint32_t b0 = packbf(make_float2(W[(size_t)k0 * TT + n],
                                     W[(size_t)(k0 + 1) * TT + n]));
    uint32_t b1 = packbf(make_float2(W[(size_t)(k0 + 8) * TT + n],
                                     W[(size_t)(k0 + 9) * TT + n]));
    int s2 = s >> 1, h = s & 1;
    uint32_t* out = reinterpret_cast<uint32_t*>(&g_Wfrag[(s2 * 6 + j) * 32 + lane]);
    out[h * 2 + 0] = b0;
    out[h * 2 + 1] = b1;
}

// ---------------------------------------------------------------------------
// GEMM via mma.sync bf16 + cp.async 4-stage smem pipeline (R12-exact, 75us).
// ---------------------------------------------------------------------------
__global__ __launch_bounds__(256)
void gemm_mma(const float* __restrict__ H, const float* __restrict__ bias) {
    __shared__ __align__(16) float sA[STG * 128 * RSTRIDE];   // 40 KB

    const int tid  = threadIdx.x;
    const int w    = tid >> 5;
    const int lane = tid & 31;
    const int c    = lane & 3;
    const int g    = lane >> 2;

    const int crow  = tid >> 1;
    const int chalf = tid & 1;
    const float* gsrc = H + ((size_t)blockIdx.x * 128 + crow) * UU + chalf * 8;
    const uint32_t sbase = smem_u32(sA);
    const uint32_t cdst  = sbase + (crow * RSTRIDE + chalf * 8) * 4;

    const size_t m0 = (size_t)blockIdx.x * 128 + w * 16;
    const float* srow = sA + (w * 16 + g) * RSTRIDE + 2 * c;

    float2 bias2[6];
#pragma unroll
    for (int j = 0; j < 6; j++)
        bias2[j] = *reinterpret_cast<const float2*>(bias + 8 * j + 2 * c);

    float d[6][4];
#pragma unroll
    for (int j = 0; j < 6; j++)
#pragma unroll
        for (int i = 0; i < 4; i++) d[j][i] = 0.f;

#pragma unroll
    for (int ch = 0; ch < 3; ch++) {
        uint32_t dst = cdst + ch * (128 * RSTRIDE * 4);
        const float* src = gsrc + ch * KCH;
        cp16(dst, src);
        cp16(dst + 16, src + 4);
        CP_COMMIT();
    }

    for (int s2 = 0; s2 < 32; s2++) {
        uint4 bf[6];
        {
            const uint4* bp = g_Wfrag + (size_t)(s2 * 6) * 32 + lane;
#pragma unroll
            for (int j = 0; j < 6; j++) bf[j] = bp[j * 32];
        }
        {
            const int ch = 2 * s2;
            if (ch < NCH - 2) { CP_WAIT(2); } else { CP_WAIT(0); }
            __syncthreads();
            if (ch + 3 < NCH) {
                uint32_t dst = cdst + ((ch + 3) & 3) * (128 * RSTRIDE * 4);
                const float* src = gsrc + (ch + 3) * KCH;
                cp16(dst, src);
                cp16(dst + 16, src + 4);
                CP_COMMIT();
            }
            const float* sp = srow + (ch & 3) * (128 * RSTRIDE);
            float2 f0 = *reinterpret_cast<const float2*>(sp);
            float2 f1 = *reinterpret_cast<const float2*>(sp + 8 * RSTRIDE);
            float2 f2 = *reinterpret_cast<const float2*>(sp + 8);
            float2 f3 = *reinterpret_cast<const float2*>(sp + 8 * RSTRIDE + 8);
            uint32_t a0 = packbf(f0), a1 = packbf(f1);
            uint32_t a2 = packbf(f2), a3 = packbf(f3);
#pragma unroll
            for (int j = 0; j < 6; j++)
                mma16816(d[j], a0, a1, a2, a3, bf[j].x, bf[j].y);
        }
        {
            const int ch = 2 * s2 + 1;
            if (ch < NCH - 2) { CP_WAIT(2); } else { CP_WAIT(0); }
            __syncthreads();
            if (ch + 3 < NCH) {
                uint32_t dst = cdst + ((ch + 3) & 3) * (128 * RSTRIDE * 4);
                const float* src = gsrc + (ch + 3) * KCH;
                cp16(dst, src);
                cp16(dst + 16, src + 4);
                CP_COMMIT();
            }
            const float* sp = srow + (ch & 3) * (128 * RSTRIDE);
            float2 f0 = *reinterpret_cast<const float2*>(sp);
            float2 f1 = *reinterpret_cast<const float2*>(sp + 8 * RSTRIDE);
            float2 f2 = *reinterpret_cast<const float2*>(sp + 8);
            float2 f3 = *reinterpret_cast<const float2*>(sp + 8 * RSTRIDE + 8);
            uint32_t a0 = packbf(f0), a1 = packbf(f1);
            uint32_t a2 = packbf(f2), a3 = packbf(f3);
#pragma unroll
            for (int j = 0; j < 6; j++)
                mma16816(d[j], a0, a1, a2, a3, bf[j].z, bf[j].w);
        }
    }

    float* dst0 = g_scores + (m0 + g) * TT;
    float* dst1 = dst0 + 8 * TT;
#pragma unroll
    for (int j = 0; j < 6; j++) {
        *reinterpret_cast<float2*>(dst0 + 8 * j + 2 * c) =
            make_float2(d[j][0] + bias2[j].x, d[j][1] + bias2[j].y);
        *reinterpret_cast<float2*>(dst1 + 8 * j + 2 * c) =
            make_float2(d[j][2] + bias2[j].x, d[j][3] + bias2[j].y);
    }
}

// 2-state dot: E columns Ea/Eb (48 regs each), v from smem (broadcast LDS.128)
__device__ __forceinline__ void dot2x48(const float* Ea, const float* Eb,
                                        const float* vec,
                                        float& dotA, float& dotB, float& v0) {
    const float4* vp = reinterpret_cast<const float4*>(vec);
    float4 q[12];
#pragma unroll
    for (int j = 0; j < 12; j++) q[j] = vp[j];
    v0 = q[0].x;
    float a0 = q[0].x * Ea[0], a1 = q[0].y * Ea[1];
    float a2 = q[0].z * Ea[2], a3 = q[0].w * Ea[3];
    float b0 = q[0].x * Eb[0], b1 = q[0].y * Eb[1];
    float b2 = q[0].z * Eb[2], b3 = q[0].w * Eb[3];
#pragma unroll
    for (int j = 1; j < 12; j++) {
        a0 = fmaf(q[j].x, Ea[4 * j + 0], a0);
        a1 = fmaf(q[j].y, Ea[4 * j + 1], a1);
        a2 = fmaf(q[j].z, Ea[4 * j + 2], a2);
        a3 = fmaf(q[j].w, Ea[4 * j + 3], a3);
        b0 = fmaf(q[j].x, Eb[4 * j + 0], b0);
        b1 = fmaf(q[j].y, Eb[4 * j + 1], b1);
        b2 = fmaf(q[j].z, Eb[4 * j + 2], b2);
        b3 = fmaf(q[j].w, Eb[4 * j + 3], b3);
    }
    dotA = (a0 + a1) + (a2 + a3);
    dotB = (b0 + b1) + (b2 + b3);
}

// ---------------------------------------------------------------------------
// BARRIER-FREE bidirectional scan + numerator. 96 threads (3 warps)/block:
//   warp 0: forward alpha scan, m = (len-1)/2 steps. Lane l owns states
//           2l, 2l+1 (l<24 active); E columns in 96 regs; v in a smem double
//           buffer; ONE __syncwarp per step (no __syncthreads in any loop).
//   warp 1: backward beta scan, K = len-1-m steps, independent of warp 0.
//   warp 2: numerator.
// Single final __syncthreads joins all three; thread 0 combines.
// logZ = (Cf+Cb)·ln2 + log(sum_t alpha_m[t]·beta_m[t]);  out = num - logZ.
// ---------------------------------------------------------------------------
__global__ __launch_bounds__(96, 1)
void scan_kernel(const float* __restrict__ trans,
                 const float* __restrict__ startT,
                 const float* __restrict__ endT,
                 const int* __restrict__ tag,
                 const int* __restrict__ s_len,
                 float* __restrict__ out) {
    const int b = blockIdx.x;
    const int tid = threadIdx.x;
    const int wid = tid >> 5;
    const int l   = tid & 31;
    __shared__ __align__(16) float vf[2][64];
    __shared__ __align__(16) float vb[2][64];
    __shared__ float redf[64];
    __shared__ float redb[64];
    __shared__ float s_num;
    __shared__ int   s_CeB;

    const int len = s_len[b];
    const int m   = (len - 1) >> 1;      // meeting point
    const int K   = len - 1 - m;
    const float* sc = g_scores + (size_t)b * SS * TT;

    if (wid == 0) {
        // ---------------- FORWARD warp: lane owns states 2l, 2l+1 ----------
        const bool act = l < 24;
        const int t0 = act ? 2 * l : 0;

        float Ea[TT], Eb[TT];
#pragma unroll
        for (int k = 0; k < TT; k++) {
            float ea = __expf(trans[k * TT + t0]);
            float eb = __expf(trans[k * TT + t0 + 1]);
            Ea[k] = act ? ea : 0.f;
            Eb[k] = act ? eb : 0.f;
        }
        // init alpha_0
        float2 em0 = *reinterpret_cast<const float2*>(sc + t0);
        float af0 = act ? __expf(startT[t0] + em0.x) : 0.f;
        float af1 = act ? __expf(startT[t0 + 1] + em0.y) : 0.f;
        *reinterpret_cast<float2*>(&vf[0][2 * l]) = make_float2(af0, af1);
        int Ce = 0;

        // emission pipeline (float2 per step covers both states)
        float2 p1 = *reinterpret_cast<const float2*>(sc + 1 * TT + t0);
        float2 x1 = make_float2(__expf(p1.x), __expf(p1.y));
        float2 eA = *reinterpret_cast<const float2*>(sc + 2 * TT + t0);
        float2 eB = *reinterpret_cast<const float2*>(sc + 3 * TT + t0);
        __syncwarp();

        int cur = 0;
        for (int i = 0; i < m; ++i) {
            const int s = i + 1;
            float2 ex = x1;
            x1.x = __expf(eA.x); x1.y = __expf(eA.y);
            eA = eB;
            int sp = s + 3; if (sp > SS - 1) sp = SS - 1;
            eB = *reinterpret_cast<const float2*>(sc + sp * TT + t0);

            float dA, dB, v0;
            dot2x48(Ea, Eb, vf[cur], dA, dB, v0);

            int eb = (__float_as_int(v0) >> 23) & 0xff;
            Ce += eb - 127;
            float scl = __int_as_float((254 - eb) << 23);
            af0 = dA * scl * ex.x;
            af1 = dB * scl * ex.y;

            *reinterpret_cast<float2*>(&vf[cur ^ 1][2 * l]) = make_float2(af0, af1);
            __syncwarp();
            cur ^= 1;
        }
        *reinterpret_cast<float2*>(&redf[2 * l]) = make_float2(af0, af1);
        __syncthreads();                               // single block barrier

        if (tid == 0) {
            float ssum = 0.f;
#pragma unroll
            for (int k = 0; k < TT; k++) ssum += redf[k] * redb[k];
            float logZ = (float)(Ce + s_CeB) * 0.6931471805599453f + __logf(ssum);
            out[b] = s_num - logZ;
        }
    } else if (wid == 1) {
        // ---------------- BACKWARD warp: lane owns states 2l, 2l+1 ---------
        const bool act = l < 24;
        const int u0 = act ? 2 * l : 0;

        float Ea[TT], Eb[TT];
#pragma unroll
        for (int k = 0; k < TT; k++) {
            float ea = __expf(trans[u0 * TT + k]);         // row u0
            float eb = __expf(trans[(u0 + 1) * TT + k]);   // row u0+1
            Ea[k] = act ? ea : 0.f;
            Eb[k] = act ? eb : 0.f;
        }
        // init w_{len-1} = exp(emit_{len-1} + end)
        float2 emL = *reinterpret_cast<const float2*>(sc + (size_t)(len - 1) * TT + u0);
        float bw0 = act ? __expf(emL.x + endT[u0]) : 0.f;
        float bw1 = act ? __expf(emL.y + endT[u0 + 1]) : 0.f;
        *reinterpret_cast<float2*>(&vb[0][2 * l]) = make_float2(bw0, bw1);
        int Ce = 0;

        int q1 = len - 2; if (q1 < 0) q1 = 0;
        int q2 = len - 3; if (q2 < 0) q2 = 0;
        int q3 = len - 4; if (q3 < 0) q3 = 0;
        float2 p1 = *reinterpret_cast<const float2*>(sc + (size_t)q1 * TT + u0);
        float2 x1 = make_float2(__expf(p1.x), __expf(p1.y));
        float2 eA = *reinterpret_cast<const float2*>(sc + (size_t)q2 * TT + u0);
        float2 eB = *reinterpret_cast<const float2*>(sc + (size_t)q3 * TT + u0);
        __syncwarp();

        int cur = 0;
        for (int i = 0; i < K; ++i) {
            const int s = len - 2 - i;                 // s: len-2 .. m
            float2 ex = x1;
            x1.x = __expf(eA.x); x1.y = __expf(eA.y);
            eA = eB;
            int sp = s - 3; if (sp < 0) sp = 0;
            eB = *reinterpret_cast<const float2*>(sc + (size_t)sp * TT + u0);

            float dA, dB, w0;
            dot2x48(Ea, Eb, vb[cur], dA, dB, w0);

            int eb = (__float_as_int(w0) >> 23) & 0xff;
            Ce += eb - 127;
            float scl = __int_as_float((254 - eb) << 23);
            if (s > m) { bw0 = dA * scl * ex.x; bw1 = dB * scl * ex.y; }
            else       { bw0 = dA * scl;        bw1 = dB * scl;        }

            *reinterpret_cast<float2*>(&vb[cur ^ 1][2 * l]) = make_float2(bw0, bw1);
            __syncwarp();
            cur ^= 1;
        }
        if (K == 0) {   // len == 1: beta = exp(end)
            bw0 = act ? __expf(endT[u0]) : 0.f;
            bw1 = act ? __expf(endT[u0 + 1]) : 0.f;
        }
        *reinterpret_cast<float2*>(&redb[2 * l]) = make_float2(bw0, bw1);
        if (l == 0) s_CeB = Ce;
        __syncthreads();                               // single block barrier
    } else {
        // ---------------- numerator warp ----------------
        const int* tg = tag + b * SS;
        float local = 0.f;
        for (int s = l; s < len; s += 32) {
            int tc2 = tg[s];
            local += sc[s * TT + tc2];
            if (s >= 1) local += trans[tg[s - 1] * TT + tc2];
        }
        if (l == 0) local += startT[tg[0]] + endT[tg[len - 1]];
#pragma unroll
        for (int o = 16; o > 0; o >>= 1)
            local += __shfl_down_sync(0xffffffffu, local, o);
        if (l == 0) s_num = local;
        __syncthreads();                               // single block barrier
    }
}

// ---------------------------------------------------------------------------
// Launch. Inputs: H, W, b, start_transitions, end_transitions, transitions,
// tag(int32), s_len(int32), w_mask (unused: mask == s < s_len).
// ---------------------------------------------------------------------------
extern "C" void kernel_launch(void* const* d_in, const int* in_sizes, int n_in,
                              void* d_out, int out_size) {
    const float* H      = (const float*)d_in[0];
    const float* W      = (const float*)d_in[1];
    const float* bias   = (const float*)d_in[2];
    const float* startT = (const float*)d_in[3];
    const float* endT   = (const float*)d_in[4];
    const float* trans  = (const float*)d_in[5];
    const int*   tag    = (const int*)d_in[6];
    const int*   s_len  = (const int*)d_in[7];
    (void)in_sizes; (void)n_in; (void)out_size;
    float* out = (float*)d_out;

    wfrag_kernel<<<48, 256>>>(W);
    gemm_mma<<<(BB * SS) / 128, 256>>>(H, bias);
    scan_kernel<<<BB, 96>>>(trans, startT, endT, tag, s_len, out);
}